// round 3
// baseline (speedup 1.0000x reference)
#include <cuda_runtime.h>
#include <cuda_bf16.h>

// Problem constants
#define NB 128          // graphs
#define NN 512          // nodes per graph
#define NNODES (NB*NN)  // 65536
#define NE 524288       // edges
#define F_IN 128
#define H1 64
#define H2 128
#define NC 10
#define KSEL 410        // ceil(0.8*512)
#define NMASK (NNODES - 1)

// ---------------- scratch (static device globals; no allocation) ----------------
__device__ __align__(16) int   g_cnt[NNODES];
__device__ __align__(16) int   g_fill[NNODES];
__device__ __align__(16) int   g_rowptr[NNODES + 1];
__device__ __align__(16) int   g_col[NE];
__device__ __align__(16) float g_dis[NNODES];
__device__ __align__(16) float g_h1[NNODES * H1];
__device__ __align__(16) float g_out1[NNODES * H1];
__device__ __align__(16) float g_a2[NNODES * H1];
__device__ __align__(16) float g_out2[NNODES * H2];
__device__ __align__(16) float g_score[NNODES];
__device__ __align__(16) float g_gmax[NB * H2];

// ---------------- CSR build ----------------
__global__ void k_zero() {
    int i = blockIdx.x * blockDim.x + threadIdx.x;
    if (i < NNODES) { g_cnt[i] = 0; g_fill[i] = 0; }
}

// edge_index is int32 (JAX x64 disabled): layout [2, NE]
__global__ void k_count(const int* __restrict__ ei) {
    int e = blockIdx.x * blockDim.x + threadIdx.x;
    if (e < NE) {
        int d = ei[NE + e] & NMASK;
        atomicAdd(&g_cnt[d], 1);
    }
}

// single-block scan of 65536 counts -> rowptr, plus dis = rsqrt(deg+1)
__global__ void k_scan() {
    __shared__ int part[1024];
    int t = threadIdx.x;
    int base = t * 64;
    int s = 0;
    for (int i = 0; i < 64; i++) s += g_cnt[base + i];
    part[t] = s;
    __syncthreads();
    for (int off = 1; off < 1024; off <<= 1) {
        int v = (t >= off) ? part[t - off] : 0;
        __syncthreads();
        part[t] += v;
        __syncthreads();
    }
    int run = (t == 0) ? 0 : part[t - 1];
    for (int i = 0; i < 64; i++) {
        int c = g_cnt[base + i];
        g_rowptr[base + i] = run;
        g_dis[base + i] = rsqrtf((float)(c + 1));   // +1 self loop
        run += c;
    }
    if (t == 1023) g_rowptr[NNODES] = run;
}

__global__ void k_scatter(const int* __restrict__ ei) {
    int e = blockIdx.x * blockDim.x + threadIdx.x;
    if (e < NE) {
        int s = ei[e] & NMASK;
        int d = ei[NE + e] & NMASK;
        int pos = atomicAdd(&g_fill[d], 1);
        g_col[g_rowptr[d] + pos] = s;
    }
}

// ---------------- GEMM1: g_h1[65536,64] = X[65536,128] @ W1[128,64] ----------------
// tile 32 rows x 64 cols, block (16,8)=128 thr, each thread 4 rows x 4 cols
__global__ void k_gemm1(const float* __restrict__ X, const float* __restrict__ W) {
    __shared__ float Ws[F_IN * H1];    // 32 KB
    __shared__ float Xs[32 * F_IN];    // 16 KB
    int tx = threadIdx.x, ty = threadIdx.y;
    int t = ty * 16 + tx;
    int row0 = blockIdx.x * 32;

    float4* Ws4 = (float4*)Ws;
    const float4* Wg = (const float4*)W;
    #pragma unroll
    for (int l = t; l < (F_IN * H1) / 4; l += 128) Ws4[l] = Wg[l];

    float4* Xs4 = (float4*)Xs;
    const float4* Xg = (const float4*)(X + (size_t)row0 * F_IN);
    #pragma unroll
    for (int l = t; l < (32 * F_IN) / 4; l += 128) Xs4[l] = Xg[l];
    __syncthreads();

    float acc[4][4];
    #pragma unroll
    for (int r = 0; r < 4; r++)
        #pragma unroll
        for (int c = 0; c < 4; c++) acc[r][c] = 0.f;

    #pragma unroll 4
    for (int k = 0; k < F_IN; k += 4) {
        float4 xq[4];
        #pragma unroll
        for (int r = 0; r < 4; r++) xq[r] = Xs4[(ty * 4 + r) * (F_IN / 4) + k / 4];
        #pragma unroll
        for (int kk = 0; kk < 4; kk++) {
            float4 w = Ws4[(k + kk) * (H1 / 4) + tx];
            #pragma unroll
            for (int r = 0; r < 4; r++) {
                float xv = (kk == 0) ? xq[r].x : (kk == 1) ? xq[r].y : (kk == 2) ? xq[r].z : xq[r].w;
                acc[r][0] += xv * w.x;
                acc[r][1] += xv * w.y;
                acc[r][2] += xv * w.z;
                acc[r][3] += xv * w.w;
            }
        }
    }
    #pragma unroll
    for (int r = 0; r < 4; r++) {
        float4 o = make_float4(acc[r][0], acc[r][1], acc[r][2], acc[r][3]);
        ((float4*)g_h1)[((size_t)(row0 + ty * 4 + r) * H1 + tx * 4) / 4] = o;
    }
}

// ---------------- gather (symmetric-norm aggregation), 64 features ----------------
// PASS 0: g_out1 = relu( Agg(g_h1) + b1 )
// PASS 1: g_a2   = Agg(g_out1)
// Agg(h)[v] = sum_{s in in(v)} dis[s]*dis[v]*h[s] + dis[v]^2 * h[v]
template <int PASS>
__global__ void k_gather64(const float* __restrict__ bias) {
    const float* __restrict__ h   = (PASS == 0) ? g_h1   : g_out1;
    float* __restrict__       out = (PASS == 0) ? g_out1 : g_a2;
    int warp = threadIdx.x >> 5, lane = threadIdx.x & 31;
    int v = blockIdx.x * 8 + warp;
    float dv = g_dis[v];
    int beg = g_rowptr[v], end = g_rowptr[v + 1];
    float a0 = dv * dv * h[(size_t)v * H1 + lane];
    float a1 = dv * dv * h[(size_t)v * H1 + 32 + lane];
    for (int e = beg; e < end; e++) {
        int s = g_col[e];
        float w = dv * g_dis[s];
        a0 += w * h[(size_t)s * H1 + lane];
        a1 += w * h[(size_t)s * H1 + 32 + lane];
    }
    if (PASS == 0) {
        a0 = fmaxf(a0 + bias[lane], 0.f);
        a1 = fmaxf(a1 + bias[32 + lane], 0.f);
    }
    out[(size_t)v * H1 + lane] = a0;
    out[(size_t)v * H1 + 32 + lane] = a1;
}

// ---------------- GEMM2: g_out2 = relu(g_a2[65536,64] @ W2[64,128] + b2) ----------------
// tile 64 rows x 128 cols, block (32,8)=256 thr, each thread 8 rows x 4 cols
__global__ void k_gemm2(const float* __restrict__ W, const float* __restrict__ bias) {
    __shared__ float Ws[H1 * H2];   // 32 KB
    __shared__ float Xs[64 * H1];   // 16 KB
    int tx = threadIdx.x, ty = threadIdx.y;
    int t = ty * 32 + tx;
    int row0 = blockIdx.x * 64;

    float4* Ws4 = (float4*)Ws;
    const float4* Wg = (const float4*)W;
    #pragma unroll
    for (int l = t; l < (H1 * H2) / 4; l += 256) Ws4[l] = Wg[l];

    float4* Xs4 = (float4*)Xs;
    const float4* Ag = (const float4*)(g_a2 + (size_t)row0 * H1);
    #pragma unroll
    for (int l = t; l < (64 * H1) / 4; l += 256) Xs4[l] = Ag[l];
    __syncthreads();

    float acc[8][4];
    #pragma unroll
    for (int r = 0; r < 8; r++)
        #pragma unroll
        for (int c = 0; c < 4; c++) acc[r][c] = 0.f;

    #pragma unroll 2
    for (int k = 0; k < H1; k += 4) {
        float4 xq[8];
        #pragma unroll
        for (int r = 0; r < 8; r++) xq[r] = Xs4[(ty * 8 + r) * (H1 / 4) + k / 4];
        #pragma unroll
        for (int kk = 0; kk < 4; kk++) {
            float4 w = Ws4[(k + kk) * (H2 / 4) + tx];
            #pragma unroll
            for (int r = 0; r < 8; r++) {
                float xv = (kk == 0) ? xq[r].x : (kk == 1) ? xq[r].y : (kk == 2) ? xq[r].z : xq[r].w;
                acc[r][0] += xv * w.x;
                acc[r][1] += xv * w.y;
                acc[r][2] += xv * w.z;
                acc[r][3] += xv * w.w;
            }
        }
    }
    float4 b = ((const float4*)bias)[tx];
    #pragma unroll
    for (int r = 0; r < 8; r++) {
        float4 o;
        o.x = fmaxf(acc[r][0] + b.x, 0.f);
        o.y = fmaxf(acc[r][1] + b.y, 0.f);
        o.z = fmaxf(acc[r][2] + b.z, 0.f);
        o.w = fmaxf(acc[r][3] + b.w, 0.f);
        ((float4*)g_out2)[((size_t)(row0 + ty * 8 + r) * H2 + tx * 4) / 4] = o;
    }
}

// ---------------- score = (out2 . pool_w) / ||pool_w||, warp per node ----------------
__global__ void k_score(const float* __restrict__ pw) {
    int warp = threadIdx.x >> 5, lane = threadIdx.x & 31;
    int v = blockIdx.x * 8 + warp;
    float s = 0.f, nn = 0.f;
    #pragma unroll
    for (int j = 0; j < 4; j++) {
        float p = pw[lane + 32 * j];
        nn += p * p;
        s += p * g_out2[(size_t)v * H2 + lane + 32 * j];
    }
    #pragma unroll
    for (int off = 16; off > 0; off >>= 1) {
        s  += __shfl_xor_sync(0xffffffffu, s, off);
        nn += __shfl_xor_sync(0xffffffffu, nn, off);
    }
    if (lane == 0) g_score[v] = s * rsqrtf(nn);
}

// ---------------- top-K selection + gated global max pool, one block per graph ----------------
__global__ void k_pool() {
    __shared__ float s[NN];
    __shared__ float gate[NN];
    __shared__ int   sel[NN];
    __shared__ float red[NN];
    int b = blockIdx.x;
    int t = threadIdx.x;           // 512 threads
    float v = g_score[(size_t)b * NN + t];
    s[t] = v;
    __syncthreads();
    int rank = 0;
    for (int j = 0; j < NN; j++) {
        float u = s[j];
        rank += (u > v) || (u == v && j < t);
    }
    sel[t] = (rank < KSEL);
    gate[t] = tanhf(v);
    __syncthreads();
    int f = t & 127, ch = t >> 7;  // 4 chunks of 128 nodes each
    float m = -INFINITY;
    const float* base = g_out2 + ((size_t)b * NN) * H2;
    for (int i = ch * 128; i < ch * 128 + 128; i++) {
        if (sel[i]) m = fmaxf(m, base[(size_t)i * H2 + f] * gate[i]);
    }
    red[t] = m;
    __syncthreads();
    if (ch == 0) {
        float mm = fmaxf(fmaxf(red[f], red[f + 128]), fmaxf(red[f + 256], red[f + 384]));
        g_gmax[(size_t)b * H2 + f] = mm;
    }
}

// ---------------- FC + log_softmax, one thread per graph ----------------
__global__ void k_fc(const float* __restrict__ fcW, const float* __restrict__ fcb,
                     float* __restrict__ out) {
    int b = threadIdx.x;   // 128
    float acc[NC];
    #pragma unroll
    for (int c = 0; c < NC; c++) acc[c] = fcb[c];
    for (int k = 0; k < H2; k++) {
        float gv = g_gmax[(size_t)b * H2 + k];
        #pragma unroll
        for (int c = 0; c < NC; c++) acc[c] += gv * fcW[k * NC + c];
    }
    float m = acc[0];
    #pragma unroll
    for (int c = 1; c < NC; c++) m = fmaxf(m, acc[c]);
    float sum = 0.f;
    #pragma unroll
    for (int c = 0; c < NC; c++) sum += expf(acc[c] - m);
    float l = logf(sum);
    #pragma unroll
    for (int c = 0; c < NC; c++) out[(size_t)b * NC + c] = acc[c] - m - l;
}

// ---------------- launch ----------------
extern "C" void kernel_launch(void* const* d_in, const int* in_sizes, int n_in,
                              void* d_out, int out_size) {
    const float* x   = (const float*)d_in[0];
    const int*   ei  = (const int*)d_in[1];    // int32! (JAX x64 disabled)
    // d_in[2] = batch (int32, unused; layout is implicit b*512+n)
    const float* W1  = (const float*)d_in[3];
    const float* b1  = (const float*)d_in[4];
    const float* W2  = (const float*)d_in[5];
    const float* b2  = (const float*)d_in[6];
    const float* pw  = (const float*)d_in[7];
    const float* fcW = (const float*)d_in[8];
    const float* fcb = (const float*)d_in[9];
    float*       out = (float*)d_out;

    k_zero<<<NNODES / 256, 256>>>();
    k_count<<<NE / 256, 256>>>(ei);
    k_scan<<<1, 1024>>>();
    k_scatter<<<NE / 256, 256>>>(ei);

    k_gemm1<<<NNODES / 32, dim3(16, 8)>>>(x, W1);
    k_gather64<0><<<NNODES / 8, 256>>>(b1);
    k_gather64<1><<<NNODES / 8, 256>>>(nullptr);
    k_gemm2<<<NNODES / 64, dim3(32, 8)>>>(W2, b2);

    k_score<<<NNODES / 8, 256>>>(pw);
    k_pool<<<NB, NN>>>();
    k_fc<<<1, NB>>>(fcW, fcb, out);
}